// round 16
// baseline (speedup 1.0000x reference)
#include <cuda_runtime.h>
#include <cuda_bf16.h>
#include <cstdint>

#define NPTS 12288
#define DIM 256
#define DQK 64
#define BM 64
#define BN 64
#define NQB (NPTS / BM)     // 192 query blocks
#define NSPLIT 3
#define NTH (NPTS / BN / NSPLIT)   // 64 kv tiles per split unit
#define THREADS 512

// ---------------- global scratch ----------------
__device__ __align__(256) __nv_bfloat16 g_Qh[NPTS * DQK], g_Qm[NPTS * DQK];
__device__ __align__(256) __nv_bfloat16 g_Kh[NPTS * DQK], g_Km[NPTS * DQK];
__device__ __align__(256) __nv_bfloat16 g_Vth[DIM * NPTS], g_Vtl[DIM * NPTS];  // [feat][point]
__device__ __align__(256) float g_Op[NSPLIT * NPTS * DIM];
__device__ float g_mx[NSPLIT * NPTS];
__device__ float g_ls[NSPLIT * NPTS];

extern __shared__ char dynsmem[];

// ---------------- asm helpers (base sm_100 legal) ----------------
__device__ __forceinline__ uint32_t smem_u32(const void* p) {
    uint32_t a;
    asm("{ .reg .u64 t; cvta.to.shared.u64 t, %1; cvt.u32.u64 %0, t; }" : "=r"(a) : "l"(p));
    return a;
}
__device__ __forceinline__ void ldsm4(uint32_t* r, uint32_t addr) {
    asm volatile("ldmatrix.sync.aligned.m8n8.x4.shared.b16 {%0,%1,%2,%3}, [%4];"
                 : "=r"(r[0]), "=r"(r[1]), "=r"(r[2]), "=r"(r[3]) : "r"(addr));
}
__device__ __forceinline__ void mma16816(float* d, const uint32_t* a, const uint32_t* b) {
    asm volatile("mma.sync.aligned.m16n8k16.row.col.f32.bf16.bf16.f32 "
                 "{%0,%1,%2,%3}, {%4,%5,%6,%7}, {%8,%9}, {%0,%1,%2,%3};"
                 : "+f"(d[0]), "+f"(d[1]), "+f"(d[2]), "+f"(d[3])
                 : "r"(a[0]), "r"(a[1]), "r"(a[2]), "r"(a[3]), "r"(b[0]), "r"(b[1]));
}
#define CP16(dst_u32, src_ptr) \
    asm volatile("cp.async.cg.shared.global [%0], [%1], 16;" \
                 :: "r"(dst_u32), "l"(src_ptr) : "memory")
#define CP_COMMIT asm volatile("cp.async.commit_group;" ::: "memory")
#define CP_WAIT1  asm volatile("cp.async.wait_group 1;" ::: "memory")
#define CP_WAIT0  asm volatile("cp.async.wait_group 0;" ::: "memory")

__device__ __forceinline__ uint32_t swz(uint32_t row, uint32_t c16) {
    return row * 128u + (((c16 ^ row) & 7u) * 16u);
}
// fast exp for x <= 0 (poly exp2, no MUFU). rel err ~6e-8.
__device__ __forceinline__ float eexp(float x) {
    float t = fmaxf(x * 1.4426950408889634f, -126.0f);
    float z = t + 12582912.0f;
    int   ii = __float_as_int(z) - __float_as_int(12582912.0f);
    float fr = t - (z - 12582912.0f);
    float p = 9.61812911e-3f;
    p = fmaf(p, fr, 5.55041087e-2f);
    p = fmaf(p, fr, 2.40226507e-1f);
    p = fmaf(p, fr, 6.93147181e-1f);
    p = fmaf(p, fr, 1.0f);
    return __int_as_float(__float_as_int(p) + (ii << 23));
}
__device__ __forceinline__ uint32_t packbf(float a, float b) {
    __nv_bfloat162 v;
    v.x = __float2bfloat16(a);
    v.y = __float2bfloat16(b);
    return *reinterpret_cast<uint32_t*>(&v);
}

// ============================================================================
// Kernel 1: normalize + project. 768 blocks = (384 row-tiles x 2 column
// halves). half 0: V[0:128]+Q; half 1: V[128:256]+K.
// Thread = 4 rows x (4 V cols + 2 QK cols).
// ============================================================================
extern "C" __global__ void __launch_bounds__(256)
proj_kernel(const float* __restrict__ feat,
            const int*   __restrict__ coords,
            const float* __restrict__ tstride,
            const float* __restrict__ Wq, const float* __restrict__ bq,
            const float* __restrict__ Wk, const float* __restrict__ bk,
            const float* __restrict__ Wv, const float* __restrict__ bv)
{
    float* xs = (float*)dynsmem;            // [32][260]
    const int XS = 260;
    const int t = threadIdx.x;
    const int rbase = (blockIdx.x >> 1) * 32;
    const int half = blockIdx.x & 1;

    {   // load feature tile [32][256]
        const float4* src = (const float4*)(feat + (size_t)rbase * DIM);
        #pragma unroll
        for (int i = 0; i < 8; i++) {
            int idx = t + i * 256;
            float4 v = src[idx];
            int row = idx >> 6, col = (idx & 63) << 2;
            *(float4*)&xs[row * XS + col] = v;
        }
    }
    __syncthreads();
    {   // L2 normalize (8 threads / row)
        int r = t >> 3, q = t & 7;
        float ss = 0.f;
        #pragma unroll
        for (int i = 0; i < 8; i++) {
            float4 v = *(const float4*)&xs[r * XS + (q * 8 + i) * 4];
            ss += v.x * v.x + v.y * v.y + v.z * v.z + v.w * v.w;
        }
        ss += __shfl_xor_sync(0xffffffffu, ss, 1);
        ss += __shfl_xor_sync(0xffffffffu, ss, 2);
        ss += __shfl_xor_sync(0xffffffffu, ss, 4);
        float rn = 1.f / (sqrtf(ss) + 1e-6f);
        #pragma unroll
        for (int i = 0; i < 8; i++) {
            float4 v = *(float4*)&xs[r * XS + (q * 8 + i) * 4];
            v.x *= rn; v.y *= rn; v.z *= rn; v.w *= rn;
            *(float4*)&xs[r * XS + (q * 8 + i) * 4] = v;
        }
    }
    if (t < 96) {
        int rr = t / 3, ci = t % 3;
        float tsv = fmaxf(tstride[ci], 1e-6f);
        float c = (float)coords[(size_t)(rbase + rr) * 3 + ci] / tsv;
        xs[rr * XS + 256 + ci] = fminf(fmaxf(c, -100.f), 100.f);
    }
    __syncthreads();

    // ---- register-tiled GEMM: 4 rows x 6 cols per thread ----
    const int cg = t & 31;
    const int r0 = (t >> 5) * 4;
    const float* WVC = Wv + half * 128 + cg * 4;
    const float* WC  = (half == 0) ? (Wq + cg * 2) : (Wk + cg * 2);

    float acc[6][4];
    #pragma unroll
    for (int c = 0; c < 6; c++)
        #pragma unroll
        for (int r = 0; r < 4; r++) acc[c][r] = 0.f;

    #pragma unroll 4
    for (int i = 0; i < DIM + 3; i++) {
        float xv[4];
        #pragma unroll
        for (int r = 0; r < 4; r++) xv[r] = xs[(r0 + r) * XS + i];
        float4 wA = *(const float4*)(WVC + (size_t)i * 256);
        float2 wC = *(const float2*)(WC + (size_t)i * 64);
        #pragma unroll
        for (int r = 0; r < 4; r++) {
            acc[0][r] = fmaf(wA.x, xv[r], acc[0][r]);
            acc[1][r] = fmaf(wA.y, xv[r], acc[1][r]);
            acc[2][r] = fmaf(wA.z, xv[r], acc[2][r]);
            acc[3][r] = fmaf(wA.w, xv[r], acc[3][r]);
            acc[4][r] = fmaf(wC.x, xv[r], acc[4][r]);
            acc[5][r] = fmaf(wC.y, xv[r], acc[5][r]);
        }
    }

    // ---- epilogue: V (4 cols x 4 rows, transposed 2-way split) ----
    float4 bA = *(const float4*)(bv + half * 128 + cg * 4);
    #pragma unroll
    for (int j = 0; j < 4; j++) {
        int col = half * 128 + cg * 4 + j;
        float bb = ((float*)&bA)[j];
        uint32_t hp[2], lp[2];
        #pragma unroll
        for (int r2 = 0; r2 < 2; r2++) {
            float v0 = acc[j][2 * r2] + bb;
            float v1 = acc[j][2 * r2 + 1] + bb;
            float h0 = __bfloat162float(__float2bfloat16(v0));
            float h1 = __bfloat162float(__float2bfloat16(v1));
            hp[r2] = packbf(h0, h1);
            lp[r2] = packbf(v0 - h0, v1 - h1);
        }
        size_t base = (size_t)col * NPTS + rbase + r0;
        uint2 uh; uh.x = hp[0]; uh.y = hp[1];
        uint2 ul; ul.x = lp[0]; ul.y = lp[1];
        *(uint2*)(g_Vth + base) = uh;
        *(uint2*)(g_Vtl + base) = ul;
    }
    // ---- epilogue: Q or K (2 cols x 4 rows, 2-way split; Q scaled 0.125) ----
    {
        float2 bc2 = *(const float2*)(((half == 0) ? bq : bk) + cg * 2);
        __nv_bfloat16* Gh = (half == 0) ? g_Qh : g_Kh;
        __nv_bfloat16* Gm = (half == 0) ? g_Qm : g_Km;
        float scale = (half == 0) ? 0.125f : 1.f;
        #pragma unroll
        for (int j = 0; j < 2; j++) {
            float bb = ((float*)&bc2)[j];
            #pragma unroll
            for (int r = 0; r < 4; r++) {
                float v = (acc[4 + j][r] + bb) * scale;
                __nv_bfloat16 h = __float2bfloat16(v);
                __nv_bfloat16 m = __float2bfloat16(v - __bfloat162float(h));
                size_t idx = (size_t)(rbase + r0 + r) * DQK + cg * 2 + j;
                Gh[idx] = h; Gm[idx] = m;
            }
        }
    }
}

// ============================================================================
// Kernel 2: mma.sync flash attention, 512 threads / 16 warps.
// Warp (rg, cq): rows [rg*16,+16); S keys [cq*16,+16); PV feats [cq*64,+64).
// QK uses 3 split MMAs (hh, hm, mh — mm dropped, 2^-16-scale).
// Own key-quarter P in registers (C->A identity), other 3 via smem.
// KV-split 3, grid 576, double-buffered K+V.
// ============================================================================
#define SM_Q   0                        // Qh 8192 + Qm 8192
#define SM_P   16384                    // ph 8192 (4 rg x 16 x 128B) + pl 8192
#define SM_RED 32768                    // pmax[16][16] + psum[16][16] = 2048
#define SM_KV  34816
#define KVBUF  81920                    // Kh 0 / Km 8192 / Vh 16384 / Vl 49152
#define SMEM_ATTN (SM_KV + 2 * KVBUF)   // 198656

__device__ __forceinline__ void load_tile(uint32_t kvb, int kt, int t)
{
    #pragma unroll
    for (int c = t; c < 512; c += THREADS) {
        uint32_t row = c >> 3, c16 = c & 7;
        uint32_t d = swz(row, c16);
        CP16(kvb + d,        (const char*)(g_Kh + ((size_t)(kt * BN + row) * DQK + c16 * 8)));
        CP16(kvb + 8192 + d, (const char*)(g_Km + ((size_t)(kt * BN + row) * DQK + c16 * 8)));
    }
    #pragma unroll
    for (int c = t; c < 2048; c += THREADS) {
        uint32_t row = c >> 3, c16 = c & 7;
        uint32_t d = swz(row, c16);
        CP16(kvb + 16384 + d, (const char*)(g_Vth + ((size_t)row * NPTS + kt * BN + c16 * 8)));
        CP16(kvb + 49152 + d, (const char*)(g_Vtl + ((size_t)row * NPTS + kt * BN + c16 * 8)));
    }
}

extern "C" __global__ void __launch_bounds__(THREADS, 1)
attn_kernel()
{
    char* sm = dynsmem;
    const uint32_t sb = smem_u32(sm);
    const int t = threadIdx.x;
    const int lane = t & 31;
    const int w = t >> 5;
    const int rg = w & 3;            // row group (16 rows)
    const int cq = w >> 2;           // key quarter / feature quarter
    const int qb = blockIdx.x / NSPLIT;
    const int sp = blockIdx.x - qb * NSPLIT;
    const int kt0 = sp * NTH;
    const int qbase = qb * BM;

    // ---- stage Q planes ----
    #pragma unroll
    for (int c = t; c < 512; c += THREADS) {
        uint32_t row = c >> 3, c16 = c & 7;
        size_t e = (size_t)(qbase + row) * DQK + c16 * 8;
        uint32_t d = swz(row, c16);
        *(uint4*)(sm + SM_Q + d)        = *(const uint4*)(g_Qh + e);
        *(uint4*)(sm + SM_Q + 8192 + d) = *(const uint4*)(g_Qm + e);
    }
    load_tile(sb + SM_KV, kt0, t);
    CP_COMMIT;
    __syncthreads();

    // ---- Q A-fragments resident in registers ----
    uint32_t qh[16], qm[16];
    const int fm = lane >> 3, fr = lane & 7;
    {
        uint32_t row = rg * 16 + ((fm & 1) << 3) + fr;
        #pragma unroll
        for (int k2 = 0; k2 < 4; k2++) {
            uint32_t off = swz(row, k2 * 2 + (fm >> 1));
            ldsm4(&qh[k2 * 4], sb + SM_Q + off);
            ldsm4(&qm[k2 * 4], sb + SM_Q + 8192 + off);
        }
    }

    float o[8][4];
    #pragma unroll
    for (int i = 0; i < 8; i++)
        #pragma unroll
        for (int j = 0; j < 4; j++) o[i][j] = 0.f;
    float mA = -100.f, mB = -100.f, lA = 0.f, lB = 0.f;

    float* pmax = (float*)(sm + SM_RED);          // [16 warps][16 rows]
    float* psum = (float*)(sm + SM_RED + 1024);
    const uint32_t phoff = SM_P + rg * 2048;      // this rg's P region
    const uint32_t ploff = phoff + 8192;
    const int wi = rg * 4 + cq;

    int buf = 0;
    for (int i = 0; i < NTH; i++) {
        const uint32_t kvb = sb + SM_KV + buf * KVBUF;
        if (i + 1 < NTH) {
            load_tile(sb + SM_KV + (buf ^ 1) * KVBUF, kt0 + i + 1, t);
            CP_COMMIT;
            CP_WAIT1;
        } else {
            CP_WAIT0;
        }
        __syncthreads();

        // ========== QK^T: this warp keys [cq*16, cq*16+16) ==========
        float s[2][4], s2[2][4];
        #pragma unroll
        for (int a = 0; a < 2; a++)
            #pragma unroll
            for (int b = 0; b < 4; b++) { s[a][b] = 0.f; s2[a][b] = 0.f; }

        #pragma unroll
        for (int nt = 0; nt < 2; nt++) {
            uint32_t row = cq * 16 + nt * 8 + fr;      // key index
            uint32_t kh[8], km[8];
            #pragma unroll
            for (int P = 0; P < 2; P++) {
                uint32_t off = swz(row, P * 4 + fm);
                ldsm4(&kh[P * 4], kvb + off);
                ldsm4(&km[P * 4], kvb + 8192 + off);
            }
            #pragma unroll
            for (int k2 = 0; k2 < 4; k2++) {
                mma16816(s[nt],  &qh[k2 * 4], &kh[k2 * 2]);
                mma16816(s[nt],  &qh[k2 * 4], &km[k2 * 2]);
                mma16816(s2[nt], &qm[k2 * 4], &kh[k2 * 2]);
                // qm*km dropped: 2^-16-scale term, within error budget
            }
        }

        // ========== softmax: 4-warp max exchange ==========
        float mxA = -1e30f, mxB = -1e30f;
        #pragma unroll
        for (int nt = 0; nt < 2; nt++) {
            #pragma unroll
            for (int j = 0; j < 4; j++) {
                float v = fminf(fmaxf(s[nt][j] + s2[nt][j], -100.f), 100.f);
                s[nt][j] = v;
                if (j < 2) mxA = fmaxf(mxA, v); else mxB = fmaxf(mxB, v);
            }
        }
        mxA = fmaxf(mxA, __shfl_xor_sync(0xffffffffu, mxA, 1));
        mxA = fmaxf(mxA, __shfl_xor_sync(0xffffffffu, mxA, 2));
        mxB = fmaxf(mxB, __shfl_xor_sync(0xffffffffu, mxB, 1));
        mxB = fmaxf(mxB, __shfl_xor_sync(0xffffffffu, mxB, 2));
        if ((lane & 3) == 0) {
            pmax[wi * 16 + (lane >> 2)]     = mxA;
            pmax[wi * 16 + 8 + (lane >> 2)] = mxB;
        }
        __syncthreads();
        #pragma unroll
        for (int oc = 1; oc < 4; oc++) {
            int ow = rg * 4 + ((cq + oc) & 3);
            mxA = fmaxf(mxA, pmax[ow * 16 + (lane >> 2)]);
            mxB = fmaxf(mxB, pmax[ow * 16 + 8 + (lane >> 2)]);
        }
        float mnA = fmaxf(mA, mxA), mnB = fmaxf(mB, mxB);
        float cA = eexp(mA - mnA), cB = eexp(mB - mnB);
        mA = mnA; mB = mnB;
        #pragma unroll
        for (int i2 = 0; i2 < 8; i2++) {
            o[i2][0] *= cA; o[i2][1] *= cA; o[i2][2] *= cB; o[i2][3] *= cB;
        }

        // ========== exp; own-quarter P as A-frags AND to smem ==========
        uint32_t phO[4], plO[4];
        float tsA = 0.f, tsB = 0.f;
        {
            uint32_t rA = lane >> 2, rB = rA + 8;
            uint32_t colb = 4u * (lane & 3);
            #pragma unroll
            for (int nt = 0; nt < 2; nt++) {
                uint32_t g = cq * 2 + nt;
                float p0 = eexp(s[nt][0] - mA);
                float p1 = eexp(s[nt][1] - mA);
                float p2 = eexp(s[nt][2] - mB);
                float p3 = eexp(s[nt][3] - mB);
                tsA += p0 + p1; tsB += p2 + p3;
                float h0 = __bfloat162float(__float2bfloat16(p0));
                float h1 = __bfloat162float(__float2bfloat16(p1));
                float h2 = __bfloat162float(__float2bfloat16(p2));
                float h3 = __bfloat162float(__float2bfloat16(p3));
                uint32_t pa = packbf(h0, h1), pb = packbf(h2, h3);
                uint32_t qa = packbf(p0 - h0, p1 - h1), qb = packbf(p2 - h2, p3 - h3);
                phO[nt * 2]     = pa; phO[nt * 2 + 1] = pb;   // C->A frag identity
                plO[nt * 2]     = qa; plO[nt * 2 + 1] = qb;
                uint32_t offA = rA * 128u + (((g ^ rA) & 7u) << 4) + colb;
                uint32_t offB = rB * 128u + (((g ^ rB) & 7u) << 4) + colb;
                *(uint32_t*)(sm + phoff + offA) = pa;
                *(uint32_t*)(sm + ploff + offA) = qa;
                *(uint32_t*)(sm + phoff + offB) = pb;
                *(uint32_t*)(sm + ploff + offB) = qb;
            }
        }
        tsA += __shfl_xor_sync(0xffffffffu, tsA, 1);
        tsA += __shfl_xor_sync(0xffffffffu, tsA, 2);
        tsB += __shfl_xor_sync(0xffffffffu, tsB, 1);
        tsB += __shfl_xor_sync(0xffffffffu, tsB, 2);
        if ((lane & 3) == 0) {
            psum[wi * 16 + (lane >> 2)]     = tsA;
            psum[wi * 16 + 8 + (lane >> 2)] = tsB;
        }

        // ========== PV, own key quarter (k2 = cq), feats [cq*64,+64) =======
        #pragma unroll
        for (int p = 0; p < 4; p++) {
            uint32_t vrow = cq * 64 + p * 16 + ((fm >> 1) << 3) + fr;
            uint32_t off = swz(vrow, cq * 2 + (fm & 1));
            uint32_t vh[4], vl[4];
            ldsm4(vh, kvb + 16384 + off);
            ldsm4(vl, kvb + 49152 + off);
            #pragma unroll
            for (int s2i = 0; s2i < 2; s2i++) {
                mma16816(o[p * 2 + s2i], phO, &vh[s2i * 2]);
                mma16816(o[p * 2 + s2i], plO, &vh[s2i * 2]);
                mma16816(o[p * 2 + s2i], phO, &vl[s2i * 2]);
            }
        }
        __syncthreads();   // partner P + psum visible
        {
            float oA = 0.f, oB = 0.f;
            #pragma unroll
            for (int oc = 1; oc < 4; oc++) {
                int ow = rg * 4 + ((cq + oc) & 3);
                oA += psum[ow * 16 + (lane >> 2)];
                oB += psum[ow * 16 + 8 + (lane >> 2)];
            }
            lA = lA * cA + tsA + oA;
            lB = lB * cB + tsB + oB;
        }

        // ========== PV, partner key quarters ==========
        #pragma unroll
        for (int oc = 1; oc < 4; oc++) {
            int k2 = (cq + oc) & 3;
            uint32_t phP[4], plP[4];
            {
                uint32_t prow = ((fm & 1) << 3) + fr;
                uint32_t off = swz(prow, k2 * 2 + (fm >> 1));
                ldsm4(phP, sb + phoff + off);
                ldsm4(plP, sb + ploff + off);
            }
            #pragma unroll
            for (int p = 0; p < 4; p++) {
                uint32_t vrow = cq * 64 + p * 16 + ((fm >> 1) << 3) + fr;
                uint32_t off = swz(vrow, k2 * 2 + (fm & 1));
                uint32_t vh[4], vl[4];
                ldsm4(vh, kvb + 16384 + off);
                ldsm4(vl, kvb + 49152 + off);
                #pragma unroll
                for (int s2i = 0; s2i < 2; s2i++) {
                    mma16816(o[p * 2 + s2i], phP, &vh[s2i * 2]);
                    mma16816(o[p * 2 + s2i], plP, &vh[s2i * 2]);
                    mma16816(o[p * 2 + s2i], phP, &vl[s2i * 2]);
                }
            }
        }
        __syncthreads();   // done with this KV buffer + P region (load-bearing)
        buf ^= 1;
    }

    // ========== partial epilogue: unnormalized O + (m, l) ==========
    {
        int rA = qbase + rg * 16 + (lane >> 2);
        int rB = rA + 8;
        float* Ob = g_Op + (size_t)sp * NPTS * DIM;
        #pragma unroll
        for (int nt2 = 0; nt2 < 8; nt2++) {
            int c = cq * 64 + nt2 * 8 + (lane & 3) * 2;
            float2 oa, ob;
            oa.x = o[nt2][0]; oa.y = o[nt2][1];
            ob.x = o[nt2][2]; ob.y = o[nt2][3];
            *(float2*)(Ob + (size_t)rA * DIM + c) = oa;
            *(float2*)(Ob + (size_t)rB * DIM + c) = ob;
        }
        if (cq == 0 && (lane & 3) == 0) {
            g_mx[sp * NPTS + rA] = mA;
            g_ls[sp * NPTS + rA] = lA;
            g_mx[sp * NPTS + rB] = mB;
            g_ls[sp * NPTS + rB] = lB;
        }
    }
}

// ============================================================================
// Kernel 3: combine KV-split partials, divide, add residual.
// ============================================================================
extern "C" __global__ void __launch_bounds__(256)
reduce_kernel(const float* __restrict__ feat, float* __restrict__ out)
{
    int row = blockIdx.x;
    int c = threadIdx.x;
    float m0 = g_mx[row], m1 = g_mx[NPTS + row], m2 = g_mx[2 * NPTS + row];
    float l0 = g_ls[row], l1 = g_ls[NPTS + row], l2 = g_ls[2 * NPTS + row];
    float M = fmaxf(m0, fmaxf(m1, m2));
    float w0 = eexp(m0 - M), w1 = eexp(m1 - M), w2 = eexp(m2 - M);
    float den = 1.f / (l0 * w0 + l1 * w1 + l2 * w2 + 1e-6f);
    float v0 = g_Op[(size_t)row * DIM + c];
    float v1 = g_Op[(size_t)(NPTS + row) * DIM + c];
    float v2 = g_Op[(size_t)(2 * NPTS + row) * DIM + c];
    out[(size_t)row * DIM + c] =
        (v0 * w0 + v1 * w1 + v2 * w2) * den + feat[(size_t)row * DIM + c];
}

// ============================================================================
extern "C" void kernel_launch(void* const* d_in, const int* in_sizes, int n_in,
                              void* d_out, int out_size)
{
    (void)in_sizes; (void)n_in; (void)out_size;
    const float* feat   = (const float*)d_in[0];
    const int*   coords = (const int*)  d_in[1];
    const float* ts     = (const float*)d_in[2];
    const float* Wq     = (const float*)d_in[3];
    const float* bq     = (const float*)d_in[4];
    const float* Wk     = (const float*)d_in[5];
    const float* bk     = (const float*)d_in[6];
    const float* Wv     = (const float*)d_in[7];
    const float* bv     = (const float*)d_in[8];
    float* out = (float*)d_out;

    const int smem_proj = 32 * 260 * 4;
    cudaFuncSetAttribute(proj_kernel, cudaFuncAttributeMaxDynamicSharedMemorySize, smem_proj);
    cudaFuncSetAttribute(attn_kernel, cudaFuncAttributeMaxDynamicSharedMemorySize, SMEM_ATTN);

    proj_kernel<<<(NPTS / 32) * 2, 256, smem_proj>>>(feat, coords, ts, Wq, bq, Wk, bk, Wv, bv);
    attn_kernel<<<NQB * NSPLIT, THREADS, SMEM_ATTN>>>();
    reduce_kernel<<<NPTS, 256>>>(feat, out);
}

// round 17
// speedup vs baseline: 1.0496x; 1.0496x over previous
#include <cuda_runtime.h>
#include <cuda_bf16.h>
#include <cstdint>

#define NPTS 12288
#define DIM 256
#define DQK 64
#define BM 64
#define BN 64
#define NQB (NPTS / BM)     // 192 query blocks
#define NSPLIT 3
#define NTH (NPTS / BN / NSPLIT)   // 64 kv tiles per split unit
#define THREADS 512

// ---------------- global scratch ----------------
__device__ __align__(256) __nv_bfloat16 g_Qh[NPTS * DQK], g_Qm[NPTS * DQK];
__device__ __align__(256) __nv_bfloat16 g_Kh[NPTS * DQK], g_Km[NPTS * DQK];
__device__ __align__(256) __nv_bfloat16 g_Vth[DIM * NPTS], g_Vtl[DIM * NPTS];  // [feat][point]
__device__ __align__(256) float g_Op[NSPLIT * NPTS * DIM];
__device__ float g_mx[NSPLIT * NPTS];
__device__ float g_ls[NSPLIT * NPTS];

extern __shared__ char dynsmem[];

// ---------------- asm helpers (base sm_100 legal) ----------------
__device__ __forceinline__ uint32_t smem_u32(const void* p) {
    uint32_t a;
    asm("{ .reg .u64 t; cvta.to.shared.u64 t, %1; cvt.u32.u64 %0, t; }" : "=r"(a) : "l"(p));
    return a;
}
__device__ __forceinline__ void ldsm4(uint32_t* r, uint32_t addr) {
    asm volatile("ldmatrix.sync.aligned.m8n8.x4.shared.b16 {%0,%1,%2,%3}, [%4];"
                 : "=r"(r[0]), "=r"(r[1]), "=r"(r[2]), "=r"(r[3]) : "r"(addr));
}
__device__ __forceinline__ void mma16816(float* d, const uint32_t* a, const uint32_t* b) {
    asm volatile("mma.sync.aligned.m16n8k16.row.col.f32.bf16.bf16.f32 "
                 "{%0,%1,%2,%3}, {%4,%5,%6,%7}, {%8,%9}, {%0,%1,%2,%3};"
                 : "+f"(d[0]), "+f"(d[1]), "+f"(d[2]), "+f"(d[3])
                 : "r"(a[0]), "r"(a[1]), "r"(a[2]), "r"(a[3]), "r"(b[0]), "r"(b[1]));
}
#define CP16(dst_u32, src_ptr) \
    asm volatile("cp.async.cg.shared.global [%0], [%1], 16;" \
                 :: "r"(dst_u32), "l"(src_ptr) : "memory")
#define CP_COMMIT asm volatile("cp.async.commit_group;" ::: "memory")
#define CP_WAIT1  asm volatile("cp.async.wait_group 1;" ::: "memory")
#define CP_WAIT0  asm volatile("cp.async.wait_group 0;" ::: "memory")

__device__ __forceinline__ uint32_t swz(uint32_t row, uint32_t c16) {
    return row * 128u + (((c16 ^ row) & 7u) * 16u);
}
// fast exp for x <= 0 (poly exp2, no MUFU). rel err ~6e-8.
__device__ __forceinline__ float eexp(float x) {
    float t = fmaxf(x * 1.4426950408889634f, -126.0f);
    float z = t + 12582912.0f;
    int   ii = __float_as_int(z) - __float_as_int(12582912.0f);
    float fr = t - (z - 12582912.0f);
    float p = 9.61812911e-3f;
    p = fmaf(p, fr, 5.55041087e-2f);
    p = fmaf(p, fr, 2.40226507e-1f);
    p = fmaf(p, fr, 6.93147181e-1f);
    p = fmaf(p, fr, 1.0f);
    return __int_as_float(__float_as_int(p) + (ii << 23));
}
__device__ __forceinline__ uint32_t packbf(float a, float b) {
    __nv_bfloat162 v;
    v.x = __float2bfloat16(a);
    v.y = __float2bfloat16(b);
    return *reinterpret_cast<uint32_t*>(&v);
}

// ============================================================================
// Kernel 1 (R12/R15-measured best, 133us): normalize + project.
// 384 blocks x 32 rows, thread = 4 rows x 12 cols over [V(256)|Q(64)|K(64)].
// ============================================================================
extern "C" __global__ void __launch_bounds__(256)
proj_kernel(const float* __restrict__ feat,
            const int*   __restrict__ coords,
            const float* __restrict__ tstride,
            const float* __restrict__ Wq, const float* __restrict__ bq,
            const float* __restrict__ Wk, const float* __restrict__ bk,
            const float* __restrict__ Wv, const float* __restrict__ bv)
{
    float* xs = (float*)dynsmem;            // [32][260]
    const int XS = 260;
    const int t = threadIdx.x;
    const int rbase = blockIdx.x * 32;

    {
        const float4* src = (const float4*)(feat + (size_t)rbase * DIM);
        #pragma unroll
        for (int i = 0; i < 8; i++) {
            int idx = t + i * 256;
            float4 v = src[idx];
            int row = idx >> 6, col = (idx & 63) << 2;
            *(float4*)&xs[row * XS + col] = v;
        }
    }
    __syncthreads();
    {
        int r = t >> 3, q = t & 7;
        float ss = 0.f;
        #pragma unroll
        for (int i = 0; i < 8; i++) {
            float4 v = *(const float4*)&xs[r * XS + (q * 8 + i) * 4];
            ss += v.x * v.x + v.y * v.y + v.z * v.z + v.w * v.w;
        }
        ss += __shfl_xor_sync(0xffffffffu, ss, 1);
        ss += __shfl_xor_sync(0xffffffffu, ss, 2);
        ss += __shfl_xor_sync(0xffffffffu, ss, 4);
        float rn = 1.f / (sqrtf(ss) + 1e-6f);
        #pragma unroll
        for (int i = 0; i < 8; i++) {
            float4 v = *(float4*)&xs[r * XS + (q * 8 + i) * 4];
            v.x *= rn; v.y *= rn; v.z *= rn; v.w *= rn;
            *(float4*)&xs[r * XS + (q * 8 + i) * 4] = v;
        }
    }
    if (t < 96) {
        int rr = t / 3, ci = t % 3;
        float tsv = fmaxf(tstride[ci], 1e-6f);
        float c = (float)coords[(size_t)(rbase + rr) * 3 + ci] / tsv;
        xs[rr * XS + 256 + ci] = fminf(fmaxf(c, -100.f), 100.f);
    }
    __syncthreads();

    const int cg = t & 31;
    const int r0 = (t >> 5) * 4;
    const bool isQ = cg < 16;
    const float* WC = isQ ? (Wq + cg * 4) : (Wk + (cg - 16) * 4);

    float acc[12][4];
    #pragma unroll
    for (int c = 0; c < 12; c++)
        #pragma unroll
        for (int r = 0; r < 4; r++) acc[c][r] = 0.f;

    #pragma unroll 4
    for (int i = 0; i < DIM + 3; i++) {
        float xv[4];
        #pragma unroll
        for (int r = 0; r < 4; r++) xv[r] = xs[(r0 + r) * XS + i];
        float4 wA = *(const float4*)(Wv + (size_t)i * 256 + cg * 4);
        float4 wB = *(const float4*)(Wv + (size_t)i * 256 + 128 + cg * 4);
        float4 wC = *(const float4*)(WC + (size_t)i * 64);
        #pragma unroll
        for (int r = 0; r < 4; r++) {
            acc[0][r] = fmaf(wA.x, xv[r], acc[0][r]);
            acc[1][r] = fmaf(wA.y, xv[r], acc[1][r]);
            acc[2][r] = fmaf(wA.z, xv[r], acc[2][r]);
            acc[3][r] = fmaf(wA.w, xv[r], acc[3][r]);
            acc[4][r] = fmaf(wB.x, xv[r], acc[4][r]);
            acc[5][r] = fmaf(wB.y, xv[r], acc[5][r]);
            acc[6][r] = fmaf(wB.z, xv[r], acc[6][r]);
            acc[7][r] = fmaf(wB.w, xv[r], acc[7][r]);
            acc[8][r]  = fmaf(wC.x, xv[r], acc[8][r]);
            acc[9][r]  = fmaf(wC.y, xv[r], acc[9][r]);
            acc[10][r] = fmaf(wC.z, xv[r], acc[10][r]);
            acc[11][r] = fmaf(wC.w, xv[r], acc[11][r]);
        }
    }

    float4 bA = *(const float4*)(bv + cg * 4);
    float4 bB = *(const float4*)(bv + 128 + cg * 4);
    #pragma unroll
    for (int j = 0; j < 8; j++) {
        int col = (j < 4) ? (cg * 4 + j) : (128 + cg * 4 + (j - 4));
        float bb = (j < 4) ? ((float*)&bA)[j] : ((float*)&bB)[j - 4];
        uint32_t hp[2], lp[2];
        #pragma unroll
        for (int r2 = 0; r2 < 2; r2++) {
            float v0 = acc[j][2 * r2] + bb;
            float v1 = acc[j][2 * r2 + 1] + bb;
            float h0 = __bfloat162float(__float2bfloat16(v0));
            float h1 = __bfloat162float(__float2bfloat16(v1));
            hp[r2] = packbf(h0, h1);
            lp[r2] = packbf(v0 - h0, v1 - h1);
        }
        size_t base = (size_t)col * NPTS + rbase + r0;
        uint2 uh; uh.x = hp[0]; uh.y = hp[1];
        uint2 ul; ul.x = lp[0]; ul.y = lp[1];
        *(uint2*)(g_Vth + base) = uh;
        *(uint2*)(g_Vtl + base) = ul;
    }
    {
        const float* bC = isQ ? (bq + cg * 4) : (bk + (cg - 16) * 4);
        float4 bc4 = *(const float4*)bC;
        __nv_bfloat16* Gh = isQ ? g_Qh : g_Kh;
        __nv_bfloat16* Gm = isQ ? g_Qm : g_Km;
        int cqk = isQ ? cg * 4 : (cg - 16) * 4;
        float scale = isQ ? 0.125f : 1.f;
        #pragma unroll
        for (int j = 0; j < 4; j++) {
            float bb = ((float*)&bc4)[j];
            #pragma unroll
            for (int r = 0; r < 4; r++) {
                float v = (acc[8 + j][r] + bb) * scale;
                __nv_bfloat16 h = __float2bfloat16(v);
                __nv_bfloat16 m = __float2bfloat16(v - __bfloat162float(h));
                size_t idx = (size_t)(rbase + r0 + r) * DQK + cqk + j;
                Gh[idx] = h; Gm[idx] = m;
            }
        }
    }
}

// ============================================================================
// Kernel 2: mma.sync flash attention, 512 threads / 16 warps.
// Warp (rg, cq): rows [rg*16,+16); S keys [cq*16,+16); PV feats [cq*64,+64).
// QK: 3 split MMAs (hh, hm, mh). l cross-warp reduction deferred to epilogue.
// Own key-quarter P in registers (C->A identity), other 3 via smem.
// KV-split 3, grid 576, double-buffered K+V.
// ============================================================================
#define SM_Q   0                        // Qh 8192 + Qm 8192
#define SM_P   16384                    // ph 8192 (4 rg x 16 x 128B) + pl 8192
#define SM_RED 32768                    // pmax[16][16] + lsum[16][16] = 2048
#define SM_KV  34816
#define KVBUF  81920                    // Kh 0 / Km 8192 / Vh 16384 / Vl 49152
#define SMEM_ATTN (SM_KV + 2 * KVBUF)   // 198656

__device__ __forceinline__ void load_tile(uint32_t kvb, int kt, int t)
{
    #pragma unroll
    for (int c = t; c < 512; c += THREADS) {
        uint32_t row = c >> 3, c16 = c & 7;
        uint32_t d = swz(row, c16);
        CP16(kvb + d,        (const char*)(g_Kh + ((size_t)(kt * BN + row) * DQK + c16 * 8)));
        CP16(kvb + 8192 + d, (const char*)(g_Km + ((size_t)(kt * BN + row) * DQK + c16 * 8)));
    }
    #pragma unroll
    for (int c = t; c < 2048; c += THREADS) {
        uint32_t row = c >> 3, c16 = c & 7;
        uint32_t d = swz(row, c16);
        CP16(kvb + 16384 + d, (const char*)(g_Vth + ((size_t)row * NPTS + kt * BN + c16 * 8)));
        CP16(kvb + 49152 + d, (const char*)(g_Vtl + ((size_t)row * NPTS + kt * BN + c16 * 8)));
    }
}

extern "C" __global__ void __launch_bounds__(THREADS, 1)
attn_kernel()
{
    char* sm = dynsmem;
    const uint32_t sb = smem_u32(sm);
    const int t = threadIdx.x;
    const int lane = t & 31;
    const int w = t >> 5;
    const int rg = w & 3;            // row group (16 rows)
    const int cq = w >> 2;           // key quarter / feature quarter
    const int qb = blockIdx.x / NSPLIT;
    const int sp = blockIdx.x - qb * NSPLIT;
    const int kt0 = sp * NTH;
    const int qbase = qb * BM;

    // ---- stage Q planes ----
    #pragma unroll
    for (int c = t; c < 512; c += THREADS) {
        uint32_t row = c >> 3, c16 = c & 7;
        size_t e = (size_t)(qbase + row) * DQK + c16 * 8;
        uint32_t d = swz(row, c16);
        *(uint4*)(sm + SM_Q + d)        = *(const uint4*)(g_Qh + e);
        *(uint4*)(sm + SM_Q + 8192 + d) = *(const uint4*)(g_Qm + e);
    }
    load_tile(sb + SM_KV, kt0, t);
    CP_COMMIT;
    __syncthreads();

    // ---- Q A-fragments resident in registers ----
    uint32_t qh[16], qm[16];
    const int fm = lane >> 3, fr = lane & 7;
    {
        uint32_t row = rg * 16 + ((fm & 1) << 3) + fr;
        #pragma unroll
        for (int k2 = 0; k2 < 4; k2++) {
            uint32_t off = swz(row, k2 * 2 + (fm >> 1));
            ldsm4(&qh[k2 * 4], sb + SM_Q + off);
            ldsm4(&qm[k2 * 4], sb + SM_Q + 8192 + off);
        }
    }

    float o[8][4];
    #pragma unroll
    for (int i = 0; i < 8; i++)
        #pragma unroll
        for (int j = 0; j < 4; j++) o[i][j] = 0.f;
    float mA = -100.f, mB = -100.f, lA = 0.f, lB = 0.f;

    float* pmax = (float*)(sm + SM_RED);          // [16 warps][16 rows]
    float* lsum = (float*)(sm + SM_RED + 1024);   // epilogue-only exchange
    const uint32_t phoff = SM_P + rg * 2048;      // this rg's P region
    const uint32_t ploff = phoff + 8192;
    const int wi = rg * 4 + cq;

    int buf = 0;
    for (int i = 0; i < NTH; i++) {
        const uint32_t kvb = sb + SM_KV + buf * KVBUF;
        if (i + 1 < NTH) {
            load_tile(sb + SM_KV + (buf ^ 1) * KVBUF, kt0 + i + 1, t);
            CP_COMMIT;
            CP_WAIT1;
        } else {
            CP_WAIT0;
        }
        __syncthreads();

        // ========== QK^T: this warp keys [cq*16, cq*16+16) ==========
        float s[2][4], s2[2][4];
        #pragma unroll
        for (int a = 0; a < 2; a++)
            #pragma unroll
            for (int b = 0; b < 4; b++) { s[a][b] = 0.f; s2[a][b] = 0.f; }

        #pragma unroll
        for (int nt = 0; nt < 2; nt++) {
            uint32_t row = cq * 16 + nt * 8 + fr;      // key index
            uint32_t kh[8], km[8];
            #pragma unroll
            for (int P = 0; P < 2; P++) {
                uint32_t off = swz(row, P * 4 + fm);
                ldsm4(&kh[P * 4], kvb + off);
                ldsm4(&km[P * 4], kvb + 8192 + off);
            }
            #pragma unroll
            for (int k2 = 0; k2 < 4; k2++) {
                mma16816(s[nt],  &qh[k2 * 4], &kh[k2 * 2]);
                mma16816(s[nt],  &qh[k2 * 4], &km[k2 * 2]);
                mma16816(s2[nt], &qm[k2 * 4], &kh[k2 * 2]);
                // qm*km dropped: 2^-16-scale term, within error budget
            }
        }

        // ========== softmax: 4-warp max exchange ==========
        float mxA = -1e30f, mxB = -1e30f;
        #pragma unroll
        for (int nt = 0; nt < 2; nt++) {
            #pragma unroll
            for (int j = 0; j < 4; j++) {
                float v = fminf(fmaxf(s[nt][j] + s2[nt][j], -100.f), 100.f);
                s[nt][j] = v;
                if (j < 2) mxA = fmaxf(mxA, v); else mxB = fmaxf(mxB, v);
            }
        }
        mxA = fmaxf(mxA, __shfl_xor_sync(0xffffffffu, mxA, 1));
        mxA = fmaxf(mxA, __shfl_xor_sync(0xffffffffu, mxA, 2));
        mxB = fmaxf(mxB, __shfl_xor_sync(0xffffffffu, mxB, 1));
        mxB = fmaxf(mxB, __shfl_xor_sync(0xffffffffu, mxB, 2));
        if ((lane & 3) == 0) {
            pmax[wi * 16 + (lane >> 2)]     = mxA;
            pmax[wi * 16 + 8 + (lane >> 2)] = mxB;
        }
        __syncthreads();
        #pragma unroll
        for (int oc = 1; oc < 4; oc++) {
            int ow = rg * 4 + ((cq + oc) & 3);
            mxA = fmaxf(mxA, pmax[ow * 16 + (lane >> 2)]);
            mxB = fmaxf(mxB, pmax[ow * 16 + 8 + (lane >> 2)]);
        }
        float mnA = fmaxf(mA, mxA), mnB = fmaxf(mB, mxB);
        float cA = eexp(mA - mnA), cB = eexp(mB - mnB);
        mA = mnA; mB = mnB;
        #pragma unroll
        for (int i2 = 0; i2 < 8; i2++) {
            o[i2][0] *= cA; o[i2][1] *= cA; o[i2][2] *= cB; o[i2][3] *= cB;
        }

        // ========== exp; own-quarter P as A-frags AND to smem ==========
        uint32_t phO[4], plO[4];
        float tsA = 0.f, tsB = 0.f;
        {
            uint32_t rA = lane >> 2, rB = rA + 8;
            uint32_t colb = 4u * (lane & 3);
            #pragma unroll
            for (int nt = 0; nt < 2; nt++) {
                uint32_t g = cq * 2 + nt;
                float p0 = eexp(s[nt][0] - mA);
                float p1 = eexp(s[nt][1] - mA);
                float p2 = eexp(s[nt][2] - mB);
                float p3 = eexp(s[nt][3] - mB);
                tsA += p0 + p1; tsB += p2 + p3;
                float h0 = __bfloat162float(__float2bfloat16(p0));
                float h1 = __bfloat162float(__float2bfloat16(p1));
                float h2 = __bfloat162float(__float2bfloat16(p2));
                float h3 = __bfloat162float(__float2bfloat16(p3));
                uint32_t pa = packbf(h0, h1), pb = packbf(h2, h3);
                uint32_t qa = packbf(p0 - h0, p1 - h1), qb = packbf(p2 - h2, p3 - h3);
                phO[nt * 2]     = pa; phO[nt * 2 + 1] = pb;   // C->A frag identity
                plO[nt * 2]     = qa; plO[nt * 2 + 1] = qb;
                uint32_t offA = rA * 128u + (((g ^ rA) & 7u) << 4) + colb;
                uint32_t offB = rB * 128u + (((g ^ rB) & 7u) << 4) + colb;
                *(uint32_t*)(sm + phoff + offA) = pa;
                *(uint32_t*)(sm + ploff + offA) = qa;
                *(uint32_t*)(sm + phoff + offB) = pb;
                *(uint32_t*)(sm + ploff + offB) = qb;
            }
        }
        tsA += __shfl_xor_sync(0xffffffffu, tsA, 1);
        tsA += __shfl_xor_sync(0xffffffffu, tsA, 2);
        tsB += __shfl_xor_sync(0xffffffffu, tsB, 1);
        tsB += __shfl_xor_sync(0xffffffffu, tsB, 2);
        // deferred l: per-warp quarter-local accumulation (same global m across
        // warps in a row group -> exact; 4-warp sum moved to epilogue)
        lA = lA * cA + tsA;
        lB = lB * cB + tsB;

        // ========== PV, own key quarter (k2 = cq), feats [cq*64,+64) =======
        #pragma unroll
        for (int p = 0; p < 4; p++) {
            uint32_t vrow = cq * 64 + p * 16 + ((fm >> 1) << 3) + fr;
            uint32_t off = swz(vrow, cq * 2 + (fm & 1));
            uint32_t vh[4], vl[4];
            ldsm4(vh, kvb + 16384 + off);
            ldsm4(vl, kvb + 49152 + off);
            #pragma unroll
            for (int s2i = 0; s2i < 2; s2i++) {
                mma16816(o[p * 2 + s2i], phO, &vh[s2i * 2]);
                mma16816(o[p * 2 + s2i], plO, &vh[s2i * 2]);
                mma16816(o[p * 2 + s2i], phO, &vl[s2i * 2]);
            }
        }
        __syncthreads();   // partner P visible

        // ========== PV, partner key quarters ==========
        #pragma unroll
        for (int oc = 1; oc < 4; oc++) {
            int k2 = (cq + oc) & 3;
            uint32_t phP[4], plP[4];
            {
                uint32_t prow = ((fm & 1) << 3) + fr;
                uint32_t off = swz(prow, k2 * 2 + (fm >> 1));
                ldsm4(phP, sb + phoff + off);
                ldsm4(plP, sb + ploff + off);
            }
            #pragma unroll
            for (int p = 0; p < 4; p++) {
                uint32_t vrow = cq * 64 + p * 16 + ((fm >> 1) << 3) + fr;
                uint32_t off = swz(vrow, k2 * 2 + (fm & 1));
                uint32_t vh[4], vl[4];
                ldsm4(vh, kvb + 16384 + off);
                ldsm4(vl, kvb + 49152 + off);
                #pragma unroll
                for (int s2i = 0; s2i < 2; s2i++) {
                    mma16816(o[p * 2 + s2i], phP, &vh[s2i * 2]);
                    mma16816(o[p * 2 + s2i], plP, &vh[s2i * 2]);
                    mma16816(o[p * 2 + s2i], phP, &vl[s2i * 2]);
                }
            }
        }
        __syncthreads();   // done with this KV buffer + P region (load-bearing)
        buf ^= 1;
    }

    // ========== epilogue: cross-warp l reduction, then partial output =======
    if ((lane & 3) == 0) {
        lsum[wi * 16 + (lane >> 2)]     = lA;
        lsum[wi * 16 + 8 + (lane >> 2)] = lB;
    }
    __syncthreads();
    {
        int rA = qbase + rg * 16 + (lane >> 2);
        int rB = rA + 8;
        float* Ob = g_Op + (size_t)sp * NPTS * DIM;
        #pragma unroll
        for (int nt2 = 0; nt2 < 8; nt2++) {
            int c = cq * 64 + nt2 * 8 + (lane & 3) * 2;
            float2 oa, ob;
            oa.x = o[nt2][0]; oa.y = o[nt2][1];
            ob.x = o[nt2][2]; ob.y = o[nt2][3];
            *(float2*)(Ob + (size_t)rA * DIM + c) = oa;
            *(float2*)(Ob + (size_t)rB * DIM + c) = ob;
        }
        if (cq == 0 && (lane & 3) == 0) {
            float ltA = 0.f, ltB = 0.f;
            #pragma unroll
            for (int oc = 0; oc < 4; oc++) {
                ltA += lsum[(rg * 4 + oc) * 16 + (lane >> 2)];
                ltB += lsum[(rg * 4 + oc) * 16 + 8 + (lane >> 2)];
            }
            g_mx[sp * NPTS + rA] = mA;
            g_ls[sp * NPTS + rA] = ltA;
            g_mx[sp * NPTS + rB] = mB;
            g_ls[sp * NPTS + rB] = ltB;
        }
    }
}

// ============================================================================
// Kernel 3: combine KV-split partials, divide, add residual.
// ============================================================================
extern "C" __global__ void __launch_bounds__(256)
reduce_kernel(const float* __restrict__ feat, float* __restrict__ out)
{
    int row = blockIdx.x;
    int c = threadIdx.x;
    float m0 = g_mx[row], m1 = g_mx[NPTS + row], m2 = g_mx[2 * NPTS + row];
    float l0 = g_ls[row], l1 = g_ls[NPTS + row], l2 = g_ls[2 * NPTS + row];
    float M = fmaxf(m0, fmaxf(m1, m2));
    float w0 = eexp(m0 - M), w1 = eexp(m1 - M), w2 = eexp(m2 - M);
    float den = 1.f / (l0 * w0 + l1 * w1 + l2 * w2 + 1e-6f);
    float v0 = g_Op[(size_t)row * DIM + c];
    float v1 = g_Op[(size_t)(NPTS + row) * DIM + c];
    float v2 = g_Op[(size_t)(2 * NPTS + row) * DIM + c];
    out[(size_t)row * DIM + c] =
        (v0 * w0 + v1 * w1 + v2 * w2) * den + feat[(size_t)row * DIM + c];
}

// ============================================================================
extern "C" void kernel_launch(void* const* d_in, const int* in_sizes, int n_in,
                              void* d_out, int out_size)
{
    (void)in_sizes; (void)n_in; (void)out_size;
    const float* feat   = (const float*)d_in[0];
    const int*   coords = (const int*)  d_in[1];
    const float* ts     = (const float*)d_in[2];
    const float* Wq     = (const float*)d_in[3];
    const float* bq     = (const float*)d_in[4];
    const float* Wk     = (const float*)d_in[5];
    const float* bk     = (const float*)d_in[6];
    const float* Wv     = (const float*)d_in[7];
    const float* bv     = (const float*)d_in[8];
    float* out = (float*)d_out;

    const int smem_proj = 32 * 260 * 4;
    cudaFuncSetAttribute(proj_kernel, cudaFuncAttributeMaxDynamicSharedMemorySize, smem_proj);
    cudaFuncSetAttribute(attn_kernel, cudaFuncAttributeMaxDynamicSharedMemorySize, SMEM_ATTN);

    proj_kernel<<<NPTS / 32, 256, smem_proj>>>(feat, coords, ts, Wq, bq, Wk, bk, Wv, bv);
    attn_kernel<<<NQB * NSPLIT, THREADS, SMEM_ATTN>>>();
    reduce_kernel<<<NPTS, 256>>>(feat, out);
}